// round 2
// baseline (speedup 1.0000x reference)
#include <cuda_runtime.h>
#include <math.h>

namespace {
constexpr int B_ = 32, L_ = 32, D_ = 512, H_ = 512;
constexpr int H2_ = 1024, H5_ = 2560;
constexpr int PSLOT = 64, ZSLOT = 63;      // pool slots per batch; 63 = zero slot
constexpr int CSLOT = 96, DSLOT = 95;      // cache slots per batch; 95 = dummy
constexpr int NT0 = 1024;                  // step-0 task slots (992 real)
}

__device__ float g_poolH[B_ * PSLOT * H_];
__device__ float g_poolC[B_ * PSLOT * H_];
__device__ float g_cacheH[B_ * CSLOT * H_];
__device__ float g_cacheC[B_ * CSLOT * H_];
__device__ float g_logit[B_ * CSLOT];
__device__ float g_partial[NT0 * H5_];
__device__ int4  g_tasks[NT0];             // x=batch, y=left slot, z=right slot, w=cache slot
__device__ int   g_slotOf[B_ * L_];        // position -> pool slot
__device__ int   g_cidx[B_ * L_];          // pair index -> cache slot (uses 0..30)

__device__ __forceinline__ float sigm(float x) { return 1.f / (1.f + expf(-x)); }

// ---------------------------------------------------------------------------
__global__ void kInit(const int* __restrict__ length) {
    int t = blockIdx.x * blockDim.x + threadIdx.x;   // 0..2047
    if (t < NT0) {
        if (t < B_ * (L_ - 1)) {
            int b = t / (L_ - 1), j = t % (L_ - 1);
            if (j < length[b] - 1) g_tasks[t] = make_int4(b, j, j + 1, j);
            else                   g_tasks[t] = make_int4(b, ZSLOT, ZSLOT, DSLOT);
        } else g_tasks[t] = make_int4(0, ZSLOT, ZSLOT, DSLOT);
    } else if (t < NT0 + B_ * L_) {
        int idx = t - NT0, p = idx % L_;
        g_slotOf[idx] = p;
        g_cidx[idx]   = (p < L_ - 1) ? p : DSLOT;
    }
    for (int i = t; i < B_ * H_; i += 2048) {
        int b = i / H_, j = i % H_;
        g_poolH[(b * PSLOT + ZSLOT) * H_ + j] = 0.f;
        g_poolC[(b * PSLOT + ZSLOT) * H_ + j] = 0.f;
        g_cacheH[(b * CSLOT + DSLOT) * H_ + j] = 0.f;
        g_cacheC[(b * CSLOT + DSLOT) * H_ + j] = 0.f;
    }
    if (t < B_) g_logit[t * CSLOT + DSLOT] = 0.f;
}

// ---------------------------------------------------------------------------
// Leaf GEMM: hc = inp @ W_word + b_word. M=1024 (B*L), N=1024 (2H), K=512.
// Epilogue: h -> pool + nodes (leaf outputs), c -> pool.
// ---------------------------------------------------------------------------
__global__ void __launch_bounds__(256) kLeafGemm(const float* __restrict__ inp,
                                                 const float* __restrict__ Ww,
                                                 const float* __restrict__ bw,
                                                 float* __restrict__ nodes) {
    const int m0 = blockIdx.x * 64, n0 = blockIdx.y * 64;
    __shared__ __align__(16) float Xs[16][68];
    __shared__ __align__(16) float Ws[16][68];
    const int ty = threadIdx.x / 16, tx = threadIdx.x % 16;
    const int lm = threadIdx.x / 4,  lq = threadIdx.x % 4;
    const int wr = threadIdx.x / 16, wc = threadIdx.x % 16;
    float acc[4][4] = {};
    for (int k0 = 0; k0 < D_; k0 += 16) {
        float4 xv = *(const float4*)&inp[(m0 + lm) * D_ + k0 + lq * 4];
        Xs[lq*4+0][lm]=xv.x; Xs[lq*4+1][lm]=xv.y; Xs[lq*4+2][lm]=xv.z; Xs[lq*4+3][lm]=xv.w;
        *(float4*)&Ws[wr][wc*4] = *(const float4*)&Ww[(k0 + wr) * H2_ + n0 + wc * 4];
        __syncthreads();
#pragma unroll
        for (int kk = 0; kk < 16; kk++) {
            float4 a = *(const float4*)&Xs[kk][ty*4];
            float4 w = *(const float4*)&Ws[kk][tx*4];
            acc[0][0]+=a.x*w.x; acc[0][1]+=a.x*w.y; acc[0][2]+=a.x*w.z; acc[0][3]+=a.x*w.w;
            acc[1][0]+=a.y*w.x; acc[1][1]+=a.y*w.y; acc[1][2]+=a.y*w.z; acc[1][3]+=a.y*w.w;
            acc[2][0]+=a.z*w.x; acc[2][1]+=a.z*w.y; acc[2][2]+=a.z*w.z; acc[2][3]+=a.z*w.w;
            acc[3][0]+=a.w*w.x; acc[3][1]+=a.w*w.y; acc[3][2]+=a.w*w.z; acc[3][3]+=a.w*w.w;
        }
        __syncthreads();
    }
#pragma unroll
    for (int e = 0; e < 4; e++) {
        int m = m0 + ty * 4 + e, b = m / L_, l = m % L_;
#pragma unroll
        for (int f = 0; f < 4; f++) {
            int n = n0 + tx * 4 + f;
            float v = acc[e][f] + bw[n];
            if (n < H_) {
                g_poolH[(b * PSLOT + l) * H_ + n] = v;
                nodes[(b * 63 + l) * H_ + n] = v;
            } else {
                g_poolC[(b * PSLOT + l) * H_ + (n - H_)] = v;
            }
        }
    }
}

// ---------------------------------------------------------------------------
// Cell GEMM over task list: partial[kc][task] = [h_l | h_r] @ W_comp (chunked K).
// ---------------------------------------------------------------------------
__global__ void __launch_bounds__(256) kCellGemm(const float* __restrict__ Wc,
                                                 int taskStride) {
    const int mBase = blockIdx.x * 64, n0 = blockIdx.y * 64;
    const int kLen = H2_ / gridDim.z, k0base = blockIdx.z * kLen;
    __shared__ int sB[64], sL[64], sR[64];
    __shared__ __align__(16) float Xs[16][68];
    __shared__ __align__(16) float Ws[16][68];
    if (threadIdx.x < 64) {
        int4 tk = g_tasks[mBase + threadIdx.x];
        sB[threadIdx.x]=tk.x; sL[threadIdx.x]=tk.y; sR[threadIdx.x]=tk.z;
    }
    __syncthreads();
    const int ty = threadIdx.x / 16, tx = threadIdx.x % 16;
    const int lm = threadIdx.x / 4,  lq = threadIdx.x % 4;
    const int wr = threadIdx.x / 16, wc = threadIdx.x % 16;
    const float* baseL = &g_poolH[(sB[lm] * PSLOT + sL[lm]) * H_];
    const float* baseR = &g_poolH[(sB[lm] * PSLOT + sR[lm]) * H_];
    float acc[4][4] = {};
    for (int k0 = k0base; k0 < k0base + kLen; k0 += 16) {
        int kk4 = k0 + lq * 4;
        float4 xv = (kk4 < H_) ? *(const float4*)(baseL + kk4)
                               : *(const float4*)(baseR + (kk4 - H_));
        Xs[lq*4+0][lm]=xv.x; Xs[lq*4+1][lm]=xv.y; Xs[lq*4+2][lm]=xv.z; Xs[lq*4+3][lm]=xv.w;
        *(float4*)&Ws[wr][wc*4] = *(const float4*)&Wc[(k0 + wr) * H5_ + n0 + wc * 4];
        __syncthreads();
#pragma unroll
        for (int kk = 0; kk < 16; kk++) {
            float4 a = *(const float4*)&Xs[kk][ty*4];
            float4 w = *(const float4*)&Ws[kk][tx*4];
            acc[0][0]+=a.x*w.x; acc[0][1]+=a.x*w.y; acc[0][2]+=a.x*w.z; acc[0][3]+=a.x*w.w;
            acc[1][0]+=a.y*w.x; acc[1][1]+=a.y*w.y; acc[1][2]+=a.y*w.z; acc[1][3]+=a.y*w.w;
            acc[2][0]+=a.z*w.x; acc[2][1]+=a.z*w.y; acc[2][2]+=a.z*w.z; acc[2][3]+=a.z*w.w;
            acc[3][0]+=a.w*w.x; acc[3][1]+=a.w*w.y; acc[3][2]+=a.w*w.z; acc[3][3]+=a.w*w.w;
        }
        __syncthreads();
    }
#pragma unroll
    for (int e = 0; e < 4; e++) {
        int r = mBase + ty * 4 + e;
        float4 v = make_float4(acc[e][0], acc[e][1], acc[e][2], acc[e][3]);
        *(float4*)&g_partial[((int)blockIdx.z * taskStride + r) * H5_ + n0 + tx * 4] = v;
    }
}

// ---------------------------------------------------------------------------
// Per-task activation: sum K-chunks + bias, LSTM nonlinearity, cache h/c, logit.
// ---------------------------------------------------------------------------
__device__ void activateTask(int t, int kChunks, int stride,
                             const float* __restrict__ bc,
                             const float* __restrict__ q) {
    __shared__ float red[8];
    int4 tk = g_tasks[t];
    int b = tk.x, ls = tk.y, rs = tk.z, cs = tk.w;
    const float* cl = &g_poolC[(b * PSLOT + ls) * H_];
    const float* cr = &g_poolC[(b * PSLOT + rs) * H_];
    float* oh = &g_cacheH[(b * CSLOT + cs) * H_];
    float* oc = &g_cacheC[(b * CSLOT + cs) * H_];
    float lsum = 0.f;
    for (int j = threadIdx.x; j < H_; j += blockDim.x) {
        float g0=bc[j], g1=bc[H_+j], g2=bc[2*H_+j], g3=bc[3*H_+j], g4=bc[4*H_+j];
        for (int kc = 0; kc < kChunks; kc++) {
            const float* p = &g_partial[(kc * stride + t) * H5_];
            g0+=p[j]; g1+=p[H_+j]; g2+=p[2*H_+j]; g3+=p[3*H_+j]; g4+=p[4*H_+j];
        }
        float c = cl[j]*sigm(g1+1.f) + cr[j]*sigm(g2+1.f) + tanhf(g3)*sigm(g0);
        float h = sigm(g4) * tanhf(c);
        oh[j] = h; oc[j] = c; lsum += h * q[j];
    }
    for (int o = 16; o > 0; o >>= 1) lsum += __shfl_down_sync(0xffffffffu, lsum, o);
    if ((threadIdx.x & 31) == 0) red[threadIdx.x >> 5] = lsum;
    __syncthreads();
    if (threadIdx.x == 0) {
        float s = 0.f;
        for (int w = 0; w < 8; w++) s += red[w];
        g_logit[b * CSLOT + cs] = s;
    }
}

__global__ void __launch_bounds__(256) kActivate(const float* __restrict__ bc,
                                                 const float* __restrict__ q) {
    activateTask(blockIdx.x, 1, NT0, bc, q);
}

// ---------------------------------------------------------------------------
// Fused (optional) activation of this batch's 2 tasks + select/merge/bookkeep.
// One block per batch.
// ---------------------------------------------------------------------------
__global__ void __launch_bounds__(256) kActSelect(const int* __restrict__ length,
                                                  const float* __restrict__ bc,
                                                  const float* __restrict__ q,
                                                  float* __restrict__ nodes,
                                                  float* __restrict__ hf,
                                                  float* __restrict__ cf,
                                                  int stepI, int doAct) {
    int b = blockIdx.x, t = threadIdx.x;
    if (doAct) {
        activateTask(2 * b, 4, 64, bc, q);
        __syncthreads();
        activateTask(2 * b + 1, 4, 64, bc, q);
        __syncthreads();
    }
    __shared__ int sPos[32], sPair[31], sK;
    if (t < 32) sPos[t] = g_slotOf[b * L_ + t];
    if (t < 31) sPair[t] = g_cidx[b * L_ + t];
    __syncthreads();
    int lb = length[b];
    bool active = (stepI < lb - 1);
    if (active) {
        if (t == 0) {
            int cand = lb - 1 - stepI, k = 0;
            float best = -1e30f;
            for (int j = 0; j < cand; j++) {
                float v = g_logit[b * CSLOT + sPair[j]];
                if (v > best) { best = v; k = j; }
            }
            sK = k;
        }
        __syncthreads();
        int k = sK, cs = sPair[k], mslot = 32 + stepI;
        const float* ch = &g_cacheH[(b * CSLOT + cs) * H_];
        const float* cc = &g_cacheC[(b * CSLOT + cs) * H_];
        float* ph = &g_poolH[(b * PSLOT + mslot) * H_];
        float* pc = &g_poolC[(b * PSLOT + mslot) * H_];
        float* nd = &nodes[(b * 63 + 32 + stepI) * H_];
        for (int j = t; j < H_; j += 256) {
            float hv = ch[j], cv = cc[j];
            ph[j] = hv; pc[j] = cv; nd[j] = hv;
            if (stepI == 30) { hf[b * H_ + j] = hv; cf[b * H_ + j] = cv; }
        }
        if (t < 32) {
            int np = (t < k) ? sPos[t] : (t == k) ? mslot : (t < 31) ? sPos[t + 1] : ZSLOT;
            g_slotOf[b * L_ + t] = np;
        }
        if (t < 31) {
            int np;
            if      (t <  k - 1) np = sPair[t];
            else if (t == k - 1) np = 31 + 2 * stepI;
            else if (t == k)     np = 32 + 2 * stepI;
            else if (t < 30)     np = sPair[t + 1];
            else                 np = DSLOT;
            g_cidx[b * L_ + t] = np;
        }
        if (t == 0) {
            int A = 31 + 2 * stepI, Bc = 32 + 2 * stepI;
            g_tasks[2 * b] = (k > 0) ? make_int4(b, sPos[k - 1], mslot, A)
                                     : make_int4(b, ZSLOT, ZSLOT, DSLOT);
            int r = (k + 2 <= 31) ? sPos[k + 2] : ZSLOT;
            g_tasks[2 * b + 1] = make_int4(b, mslot, r, Bc);
        }
    } else {
        float* nd = &nodes[(b * 63 + 32 + stepI) * H_];
        if (stepI == 30) {
            int rs = sPos[0];
            const float* ph = &g_poolH[(b * PSLOT + rs) * H_];
            const float* pc = &g_poolC[(b * PSLOT + rs) * H_];
            for (int j = t; j < H_; j += 256) {
                float hv = ph[j];
                nd[j] = hv; hf[b * H_ + j] = hv; cf[b * H_ + j] = pc[j];
            }
        } else {
            int cs = sPair[0];
            const float* ch = &g_cacheH[(b * CSLOT + cs) * H_];
            for (int j = t; j < H_; j += 256) nd[j] = ch[j];
        }
        if (t == 0) {
            g_tasks[2 * b]     = make_int4(b, ZSLOT, ZSLOT, DSLOT);
            g_tasks[2 * b + 1] = make_int4(b, ZSLOT, ZSLOT, DSLOT);
        }
    }
}

// ---------------------------------------------------------------------------
extern "C" void kernel_launch(void* const* d_in, const int* in_sizes, int n_in,
                              void* d_out, int out_size) {
    const float* inp = (const float*)d_in[0];
    const int*   len = (const int*)  d_in[1];
    const float* Ww  = (const float*)d_in[2];
    const float* bw  = (const float*)d_in[3];
    const float* Wc  = (const float*)d_in[4];
    const float* bc  = (const float*)d_in[5];
    const float* q   = (const float*)d_in[6];
    float* out   = (float*)d_out;
    float* hf    = out;
    float* cf    = out + B_ * H_;
    float* nodes = out + 2 * B_ * H_;

    kInit<<<8, 256>>>(len);
    kLeafGemm<<<dim3(16, 16), 256>>>(inp, Ww, bw, nodes);
    kCellGemm<<<dim3(16, 40, 1), 256>>>(Wc, NT0);
    kActivate<<<B_ * (L_ - 1), 256>>>(bc, q);
    kActSelect<<<B_, 256>>>(len, bc, q, nodes, hf, cf, 0, 0);
    for (int i = 1; i <= L_ - 2; i++) {
        kCellGemm<<<dim3(1, 40, 4), 256>>>(Wc, 64);
        kActSelect<<<B_, 256>>>(len, bc, q, nodes, hf, cf, i, 1);
    }
}